// round 7
// baseline (speedup 1.0000x reference)
#include <cuda_runtime.h>
#include <cstdint>

#define NQ 4
#define NL 8

__device__ __align__(16) float g_T[112];   // 27 x (d0,d1,d2,pad)
__device__ volatile int g_flag = 0;        // set by block 0 when g_T valid
__device__ int g_exit = 0;                 // exit counter; last block resets flag

__device__ __forceinline__ float2 cmul(float2 a, float2 b) {
    return make_float2(fmaf(a.x, b.x, -a.y * b.y), fmaf(a.x, b.y, a.y * b.x));
}
__device__ __forceinline__ float2 cfma(float2 a, float2 b, float2 acc) {
    acc.x = fmaf(a.x, b.x, fmaf(-a.y, b.y, acc.x));
    acc.y = fmaf(a.x, b.y, fmaf(a.y, b.x, acc.y));
    return acc;
}
__device__ __forceinline__ int cnot_map(int m, int c, int t) {
    int bc = 3 - c, bt = 3 - t;
    if ((m >> bc) & 1) m ^= (1 << bt);
    return m;
}

// Setup body: builds the 81-coefficient tensor into sT (shared, as float[112])
// and mirrors it to g_T. Runs in ONE block (256 threads).
__device__ void do_setup(const float* __restrict__ w, float* __restrict__ sTf) {
    __shared__ float2 sGate[NL * NQ][4];
    __shared__ float2 sPA[NL][16];
    __shared__ float2 sPB[NL][16];
    __shared__ float2 sUa[256], sUb[256];
    __shared__ float  sG[256];
    __shared__ float  sA1[192], sA2[144];

    const int t = threadIdx.x;

    if (t < NL * NQ) {
        float phi = w[t * 3 + 0], th = w[t * 3 + 1], om = w[t * 3 + 2];
        float st, ct; __sincosf(0.5f * th, &st, &ct);
        float a = 0.5f * (phi + om), b = 0.5f * (phi - om);
        float sa, ca, sb, cb;
        __sincosf(a, &sa, &ca);
        __sincosf(b, &sb, &cb);
        sGate[t][0] = make_float2(ca * ct, -sa * ct);
        sGate[t][1] = make_float2(-cb * st, -sb * st);
        sGate[t][2] = make_float2(cb * st, -sb * st);
        sGate[t][3] = make_float2(ca * ct, sa * ct);
    }
    {
        int col = t >> 4, m = t & 15;
        sUa[t] = make_float2(col == m ? 1.0f : 0.0f, 0.0f);
    }
    __syncthreads();

    {
        int l = t >> 5, r = t & 31;
        int which = r >> 4, idx = r & 15;
        int i = idx >> 2, j = idx & 3;
        const float2* gA = sGate[l * 4 + which * 2 + 0];
        const float2* gB = sGate[l * 4 + which * 2 + 1];
        float2 v = cmul(gA[(i >> 1) * 2 + (j >> 1)], gB[(i & 1) * 2 + (j & 1)]);
        if (which) sPB[l][idx] = v; else sPA[l][idx] = v;
    }
    __syncthreads();

    float2* cur = sUa;
    float2* nxt = sUb;
    const int col = t >> 4, m = t & 15;
    const int mh = m >> 2, ml = m & 3;
    int mp = m;
    mp = cnot_map(mp, 0, 1);
    mp = cnot_map(mp, 1, 2);
    mp = cnot_map(mp, 2, 3);
    mp = cnot_map(mp, 3, 0);
    for (int l = 0; l < NL; l++) {
        float2 acc = make_float2(0.0f, 0.0f);
#pragma unroll
        for (int nh = 0; nh < 4; nh++) {
            float2 inner = make_float2(0.0f, 0.0f);
#pragma unroll
            for (int nl = 0; nl < 4; nl++)
                inner = cfma(sPB[l][ml * 4 + nl], cur[col * 16 + nh * 4 + nl], inner);
            acc = cfma(sPA[l][mh * 4 + nh], inner, acc);
        }
        nxt[col * 16 + mp] = acc;
        __syncthreads();
        float2* tmp = cur; cur = nxt; nxt = tmp;
    }

    {
        int j = t >> 4, k = t & 15;
        float hr = 0.0f, hi = 0.0f;
#pragma unroll
        for (int mm = 0; mm < 16; mm++) {
            float zz = ((mm >> 3) & 1) ? -1.0f : 1.0f;
            float2 uj = cur[j * 16 + mm], uk = cur[k * 16 + mm];
            hr += zz * (uj.x * uk.x + uj.y * uk.y);
            hi += zz * (uj.x * uk.y - uj.y * uk.x);
        }
        int q = (__popc(j) - __popc(k)) & 3;
        float gval = (q == 0) ? hr : (q == 1) ? -hi : (q == 2) ? -hr : hi;
        int gidx = 0;
#pragma unroll
        for (int wq = 0; wq < 4; wq++) {
            int bi = 3 - wq;
            int p = ((j >> bi) & 1) * 2 + ((k >> bi) & 1);
            gidx = gidx * 4 + p;
        }
        sG[gidx] = gval;
    }
    __syncthreads();

    const float V[4][3] = {{0.5f, 0.5f, 0.0f},
                           {0.0f, 0.0f, 0.5f},
                           {0.0f, 0.0f, 0.5f},
                           {0.5f, -0.5f, 0.0f}};
    if (t < 192) {
        int d = t % 3, p2 = (t / 3) & 3, p1 = (t / 12) & 3, p0 = t / 48;
        float acc = 0.0f;
#pragma unroll
        for (int p3 = 0; p3 < 4; p3++)
            acc += sG[((p0 * 4 + p1) * 4 + p2) * 4 + p3] * V[p3][d];
        sA1[t] = acc;
    }
    __syncthreads();
    if (t < 144) {
        int d = t % 3, c = (t / 3) % 3, rest = t / 9;
        int p1 = rest & 3, p0 = rest >> 2;
        float acc = 0.0f;
#pragma unroll
        for (int p2 = 0; p2 < 4; p2++)
            acc += sA1[((p0 * 4 + p1) * 4 + p2) * 3 + d] * V[p2][c];
        sA2[t] = acc;
    }
    __syncthreads();
    if (t < 108) {
        int d = t % 3, c = (t / 3) % 3, b = (t / 9) % 3, p0 = t / 27;
        float acc = 0.0f;
#pragma unroll
        for (int p1 = 0; p1 < 4; p1++)
            acc += sA2[((p0 * 4 + p1) * 3 + c) * 3 + d] * V[p1][b];
        sA1[t] = acc;
    }
    __syncthreads();
    if (t < 81) {
        int d = t % 3, c = (t / 3) % 3, b = (t / 9) % 3, a = t / 27;
        float acc = 0.0f;
#pragma unroll
        for (int p0 = 0; p0 < 4; p0++)
            acc += sA1[((p0 * 3 + b) * 3 + c) * 3 + d] * V[p0][a];
        int idx = (a * 9 + b * 3 + c) * 4 + d;
        sTf[idx] = acc;
        g_T[idx] = acc;
    } else if (t < 108) {
        int idx = (t - 81) * 4 + 3;
        sTf[idx] = 0.0f;
        g_T[idx] = 0.0f;
    }
    __syncthreads();
    if (t == 0) {
        __threadfence();
        g_flag = 1;  // release waiters
    }
}

// Fused: block 0 runs setup once; all blocks overlap their T-independent
// prologue (x loads + sincos) with it, then spin briefly on the flag.
// Strict per-launch flag lifecycle (starts 0, last block resets) keeps every
// launch doing identical work.
__global__ void __launch_bounds__(256, 4) vqc_fused(const float4* __restrict__ x,
                                                    const float* __restrict__ w,
                                                    float* __restrict__ out, int n) {
    __shared__ __align__(16) float4 sT[28];
    const int t = threadIdx.x;

    const int quads = (n + 3) >> 2;
    const int q = blockIdx.x * 256 + t;
    const int base = q * 4;
    const bool active = (q < quads);
    const bool full = (base + 3 < n);

    if (blockIdx.x == 0) {
        // Setup first: unblocks 1023 waiting blocks ASAP. Writes sT + g_T + flag.
        do_setup(w, reinterpret_cast<float*>(sT));
    }

    // ---- T-independent prologue (overlaps with block 0's setup) ----
    float c0[4], s0[4], c1[4], s1[4], c2[4], s2[4], c3[4], s3[4];
#pragma unroll
    for (int k = 0; k < 4; k++) {
        float4 v = (active && (full || base + k < n)) ? x[base + k]
                                                      : make_float4(0.f, 0.f, 0.f, 0.f);
        __sincosf(v.x, &s0[k], &c0[k]);
        __sincosf(v.y, &s1[k], &c1[k]);
        __sincosf(v.z, &s2[k], &c2[k]);
        __sincosf(v.w, &s3[k], &c3[k]);
    }

    if (blockIdx.x != 0) {
        if (t == 0) {
            while (g_flag == 0) { }   // volatile poll (L2)
            __threadfence();
        }
        __syncthreads();
        if (t < 28) sT[t] = reinterpret_cast<const float4*>(g_T)[t];
        __syncthreads();
    }

    // ---- contraction (identical to R6 main body) ----
    if (active) {
        float E[4];
#pragma unroll
        for (int u = 0; u < 9; u++) {
            const float4 t0 = sT[u * 3 + 0];
            const float4 t1 = sT[u * 3 + 1];
            const float4 t2 = sT[u * 3 + 2];
            const int a = u / 3, b = u % 3;  // compile-time under unroll
#pragma unroll
            for (int k = 0; k < 4; k++) {
                float a0 = fmaf(t0.z, s3[k], fmaf(t0.y, c3[k], t0.x));
                float a1 = fmaf(t1.z, s3[k], fmaf(t1.y, c3[k], t1.x));
                float a2 = fmaf(t2.z, s3[k], fmaf(t2.y, c3[k], t2.x));
                float r  = fmaf(a2, s2[k], fmaf(a1, c2[k], a0));
                if (a == 0 && b == 0) {
                    E[k] = r;
                } else if (a == 0) {
                    E[k] = fmaf(r, (b == 1) ? c1[k] : s1[k], E[k]);
                } else if (b == 0) {
                    E[k] = fmaf(r, (a == 1) ? c0[k] : s0[k], E[k]);
                } else {
                    float f0v = (a == 1) ? c0[k] : s0[k];
                    float f1v = (b == 1) ? c1[k] : s1[k];
                    E[k] = fmaf(r * f0v, f1v, E[k]);
                }
            }
        }

        if (full) {
            reinterpret_cast<float4*>(out)[q] = make_float4(E[0], E[1], E[2], E[3]);
        } else {
#pragma unroll
            for (int k = 0; k < 4; k++)
                if (base + k < n) out[base + k] = E[k];
        }
    }

    // ---- per-launch flag lifecycle: last block out resets state ----
    __syncthreads();
    if (t == 0) {
        int r = atomicAdd(&g_exit, 1);
        if (r == (int)gridDim.x - 1) {
            g_exit = 0;
            g_flag = 0;
            __threadfence();
        }
    }
}

extern "C" void kernel_launch(void* const* d_in, const int* in_sizes, int n_in,
                              void* d_out, int out_size) {
    const float* x = (const float*)d_in[0];        // (B, 4)
    const float* w = (const float*)d_in[1];        // (8, 4, 3)
    float* out = (float*)d_out;                    // (B,)
    int n = out_size;                              // B

    int quads = (n + 3) / 4;
    int blocks = (quads + 255) / 256;
    vqc_fused<<<blocks, 256>>>((const float4*)x, w, out, n);
}

// round 8
// speedup vs baseline: 1.0703x; 1.0703x over previous
#include <cuda_runtime.h>
#include <cstdint>

#define NQ 4
#define NL 8

__device__ __align__(16) float g_T[112];   // 27 x (d0,d1,d2,pad)

__device__ __forceinline__ float2 cmul(float2 a, float2 b) {
    return make_float2(fmaf(a.x, b.x, -a.y * b.y), fmaf(a.x, b.y, a.y * b.x));
}
__device__ __forceinline__ float2 cfma(float2 a, float2 b, float2 acc) {
    acc.x = fmaf(a.x, b.x, fmaf(-a.y, b.y, acc.x));
    acc.y = fmaf(a.x, b.y, fmaf(a.y, b.x, acc.y));
    return acc;
}
__device__ __forceinline__ int cnot_map(int m, int c, int t) {
    int bc = 3 - c, bt = 3 - t;
    if ((m >> bc) & 1) m ^= (1 << bt);
    return m;
}

// One block, 256 threads. Builds the 81-coefficient multilinear tensor T.
__global__ void vqc_setup(const float* __restrict__ w) {
    __shared__ float2 sGate[NL * NQ][4];
    __shared__ float2 sPA[NL][16];
    __shared__ float2 sPB[NL][16];
    __shared__ float2 sUa[256], sUb[256];
    __shared__ float  sG[256];
    __shared__ float  sA1[192], sA2[144];

    const int t = threadIdx.x;

    if (t < NL * NQ) {
        float phi = w[t * 3 + 0], th = w[t * 3 + 1], om = w[t * 3 + 2];
        float st, ct; __sincosf(0.5f * th, &st, &ct);
        float a = 0.5f * (phi + om), b = 0.5f * (phi - om);
        float sa, ca, sb, cb;
        __sincosf(a, &sa, &ca);
        __sincosf(b, &sb, &cb);
        sGate[t][0] = make_float2(ca * ct, -sa * ct);
        sGate[t][1] = make_float2(-cb * st, -sb * st);
        sGate[t][2] = make_float2(cb * st, -sb * st);
        sGate[t][3] = make_float2(ca * ct, sa * ct);
    }
    {
        int col = t >> 4, m = t & 15;
        sUa[t] = make_float2(col == m ? 1.0f : 0.0f, 0.0f);
    }
    __syncthreads();

    {
        int l = t >> 5, r = t & 31;
        int which = r >> 4, idx = r & 15;
        int i = idx >> 2, j = idx & 3;
        const float2* gA = sGate[l * 4 + which * 2 + 0];
        const float2* gB = sGate[l * 4 + which * 2 + 1];
        float2 v = cmul(gA[(i >> 1) * 2 + (j >> 1)], gB[(i & 1) * 2 + (j & 1)]);
        if (which) sPB[l][idx] = v; else sPA[l][idx] = v;
    }
    __syncthreads();

    float2* cur = sUa;
    float2* nxt = sUb;
    const int col = t >> 4, m = t & 15;
    const int mh = m >> 2, ml = m & 3;
    int mp = m;
    mp = cnot_map(mp, 0, 1);
    mp = cnot_map(mp, 1, 2);
    mp = cnot_map(mp, 2, 3);
    mp = cnot_map(mp, 3, 0);
    for (int l = 0; l < NL; l++) {
        float2 acc = make_float2(0.0f, 0.0f);
#pragma unroll
        for (int nh = 0; nh < 4; nh++) {
            float2 inner = make_float2(0.0f, 0.0f);
#pragma unroll
            for (int nl = 0; nl < 4; nl++)
                inner = cfma(sPB[l][ml * 4 + nl], cur[col * 16 + nh * 4 + nl], inner);
            acc = cfma(sPA[l][mh * 4 + nh], inner, acc);
        }
        nxt[col * 16 + mp] = acc;
        __syncthreads();
        float2* tmp = cur; cur = nxt; nxt = tmp;
    }

    {
        int j = t >> 4, k = t & 15;
        float hr = 0.0f, hi = 0.0f;
#pragma unroll
        for (int mm = 0; mm < 16; mm++) {
            float zz = ((mm >> 3) & 1) ? -1.0f : 1.0f;
            float2 uj = cur[j * 16 + mm], uk = cur[k * 16 + mm];
            hr += zz * (uj.x * uk.x + uj.y * uk.y);
            hi += zz * (uj.x * uk.y - uj.y * uk.x);
        }
        int q = (__popc(j) - __popc(k)) & 3;
        float gval = (q == 0) ? hr : (q == 1) ? -hi : (q == 2) ? -hr : hi;
        int gidx = 0;
#pragma unroll
        for (int wq = 0; wq < 4; wq++) {
            int bi = 3 - wq;
            int p = ((j >> bi) & 1) * 2 + ((k >> bi) & 1);
            gidx = gidx * 4 + p;
        }
        sG[gidx] = gval;
    }
    __syncthreads();

    const float V[4][3] = {{0.5f, 0.5f, 0.0f},
                           {0.0f, 0.0f, 0.5f},
                           {0.0f, 0.0f, 0.5f},
                           {0.5f, -0.5f, 0.0f}};
    if (t < 192) {
        int d = t % 3, p2 = (t / 3) & 3, p1 = (t / 12) & 3, p0 = t / 48;
        float acc = 0.0f;
#pragma unroll
        for (int p3 = 0; p3 < 4; p3++)
            acc += sG[((p0 * 4 + p1) * 4 + p2) * 4 + p3] * V[p3][d];
        sA1[t] = acc;
    }
    __syncthreads();
    if (t < 144) {
        int d = t % 3, c = (t / 3) % 3, rest = t / 9;
        int p1 = rest & 3, p0 = rest >> 2;
        float acc = 0.0f;
#pragma unroll
        for (int p2 = 0; p2 < 4; p2++)
            acc += sA1[((p0 * 4 + p1) * 4 + p2) * 3 + d] * V[p2][c];
        sA2[t] = acc;
    }
    __syncthreads();
    if (t < 108) {
        int d = t % 3, c = (t / 3) % 3, b = (t / 9) % 3, p0 = t / 27;
        float acc = 0.0f;
#pragma unroll
        for (int p1 = 0; p1 < 4; p1++)
            acc += sA2[((p0 * 4 + p1) * 3 + c) * 3 + d] * V[p1][b];
        sA1[t] = acc;
    }
    __syncthreads();
    if (t < 81) {
        int d = t % 3, c = (t / 3) % 3, b = (t / 9) % 3, a = t / 27;
        float acc = 0.0f;
#pragma unroll
        for (int p0 = 0; p0 < 4; p0++)
            acc += sA1[((p0 * 3 + b) * 3 + c) * 3 + d] * V[p0][a];
        g_T[(a * 9 + b * 3 + c) * 4 + d] = acc;
    } else if (t < 108) {
        g_T[(t - 81) * 4 + 3] = 0.0f;
    }
}

// Main: 2 samples/thread (regs ~40 -> 6 CTA/SM, 75% occ). Launched with PDL:
// prologue (x loads + sincos) runs while setup finishes; grid-dependency sync
// before reading g_T.
__global__ void __launch_bounds__(256, 6) vqc_main(const float4* __restrict__ x,
                                                   float* __restrict__ out, int n) {
    __shared__ __align__(16) float4 sT[28];
    const int t = threadIdx.x;

    const int pairs = (n + 1) >> 1;
    const int q = blockIdx.x * 256 + t;
    const int base = q * 2;
    const bool active = (q < pairs);
    const bool full = (base + 1 < n);

    // ---- T-independent prologue: overlaps with setup kernel via PDL ----
    float c0[2], s0[2], c1[2], s1[2], c2[2], s2[2], c3[2], s3[2];
#pragma unroll
    for (int k = 0; k < 2; k++) {
        float4 v = (active && (full || base + k < n)) ? x[base + k]
                                                      : make_float4(0.f, 0.f, 0.f, 0.f);
        __sincosf(v.x, &s0[k], &c0[k]);
        __sincosf(v.y, &s1[k], &c1[k]);
        __sincosf(v.z, &s2[k], &c2[k]);
        __sincosf(v.w, &s3[k], &c3[k]);
    }

    // ---- wait for setup kernel's completion (g_T visible), then stage T ----
    cudaGridDependencySynchronize();
    if (t < 28) sT[t] = reinterpret_cast<const float4*>(g_T)[t];
    __syncthreads();

    if (!active) return;

    float E[2];
#pragma unroll
    for (int u = 0; u < 9; u++) {
        const float4 t0 = sT[u * 3 + 0];
        const float4 t1 = sT[u * 3 + 1];
        const float4 t2 = sT[u * 3 + 2];
        const int a = u / 3, b = u % 3;  // compile-time under unroll
#pragma unroll
        for (int k = 0; k < 2; k++) {
            float a0 = fmaf(t0.z, s3[k], fmaf(t0.y, c3[k], t0.x));
            float a1 = fmaf(t1.z, s3[k], fmaf(t1.y, c3[k], t1.x));
            float a2 = fmaf(t2.z, s3[k], fmaf(t2.y, c3[k], t2.x));
            float r  = fmaf(a2, s2[k], fmaf(a1, c2[k], a0));
            if (a == 0 && b == 0) {
                E[k] = r;
            } else if (a == 0) {
                E[k] = fmaf(r, (b == 1) ? c1[k] : s1[k], E[k]);
            } else if (b == 0) {
                E[k] = fmaf(r, (a == 1) ? c0[k] : s0[k], E[k]);
            } else {
                float f0v = (a == 1) ? c0[k] : s0[k];
                float f1v = (b == 1) ? c1[k] : s1[k];
                E[k] = fmaf(r * f0v, f1v, E[k]);
            }
        }
    }

    if (full) {
        reinterpret_cast<float2*>(out)[q] = make_float2(E[0], E[1]);
    } else {
        out[base] = E[0];  // tail: base < n guaranteed by active
    }
}

extern "C" void kernel_launch(void* const* d_in, const int* in_sizes, int n_in,
                              void* d_out, int out_size) {
    const float* x = (const float*)d_in[0];        // (B, 4)
    const float* w = (const float*)d_in[1];        // (8, 4, 3)
    float* out = (float*)d_out;                    // (B,)
    int n = out_size;                              // B

    vqc_setup<<<1, 256>>>(w);

    int pairs = (n + 1) / 2;
    int blocks = (pairs + 255) / 256;

    // PDL: launch main immediately; it self-synchronizes on setup's completion
    // via cudaGridDependencySynchronize() after its trig prologue.
    cudaLaunchConfig_t cfg = {};
    cfg.gridDim = dim3((unsigned)blocks, 1, 1);
    cfg.blockDim = dim3(256, 1, 1);
    cfg.dynamicSmemBytes = 0;
    cfg.stream = 0;
    cudaLaunchAttribute attrs[1];
    attrs[0].id = cudaLaunchAttributeProgrammaticStreamSerialization;
    attrs[0].val.programmaticStreamSerializationAllowed = 1;
    cfg.attrs = attrs;
    cfg.numAttrs = 1;
    cudaLaunchKernelEx(&cfg, vqc_main, (const float4*)x, out, n);
}